// round 10
// baseline (speedup 1.0000x reference)
#include <cuda_runtime.h>
#include <cuda_bf16.h>

#define N_NODES 100000
#define N_EDGES 1600000
#define HID 64
#define DIN 128
#define NG 512
#define NC 10
#define NBLK 148
#define NT 1024
#define NWARP (NT / 32)
#define GSTR (NBLK * NT)
#define POOL_SPAN 24
#define TN 128
#define SMEM_DYN 98304
#define NTILE ((N_NODES + TN - 1) / TN)          // 782
#define NQ4 (N_EDGES / 4)                        // 400000
#define EU 2048
#define NEU ((NQ4 + EU - 1) / EU)                // 196
#define GU 256
#define NGU ((N_NODES + GU - 1) / GU)            // 391
#define NPU ((N_NODES + NT - 1) / NT)            // 98

typedef unsigned long long ull;

// ---------------- device scratch ----------------
__device__ int   g_degE[N_NODES];
__device__ int   g_off[N_NODES + 1];
__device__ int   g_cur[N_NODES];
__device__ int   g_csr[N_EDGES];
__device__ float g_coef[N_EDGES];
__device__ float g_dinv[N_NODES];
__device__ float g_h[N_NODES * HID];
__device__ float g_ha[N_NODES * HID];
__device__ float g_hb[N_NODES * HID];
__device__ float g_hc[N_NODES * HID];
__device__ float g_gsum[NG * HID];
__device__ int   g_gcnt[NG];
__device__ int   g_bsum[NBLK];
__device__ int   g_ticket[8];
__device__ int   g_barcnt;
__device__ volatile int g_bargen;

// ---------------- f32x2 helpers ----------------
__device__ __forceinline__ void ffma2(ull& acc, ull a, ull b) {
    asm("fma.rn.f32x2 %0, %1, %2, %3;" : "=l"(acc) : "l"(a), "l"(b), "l"(acc));
}
__device__ __forceinline__ float2 upk(ull v) {
    float2 r;
    asm("mov.b64 {%0,%1}, %2;" : "=f"(r.x), "=f"(r.y) : "l"(v));
    return r;
}
__device__ __forceinline__ ull pk(float a, float b) {
    ull r;
    asm("mov.b64 %0, {%1,%2};" : "=l"(r) : "f"(a), "f"(b));
    return r;
}

// ---------------- software grid barrier ----------------
__device__ __forceinline__ void gridbar() {
    __threadfence();
    __syncthreads();
    if (threadIdx.x == 0) {
        int gen = g_bargen;
        if (atomicAdd(&g_barcnt, 1) == NBLK - 1) {
            g_barcnt = 0;
            __threadfence();
            atomicExch((int*)&g_bargen, gen + 1);
        } else {
            while (g_bargen == gen) __nanosleep(64);
        }
        __threadfence();
    }
    __syncthreads();
}

// ---------------- GEMM tile body: 8 nodes/warp-group, 1 channel/lane ----------------
// Wt4[p][c] = (W[4p][c], W[4p+1][c], W[4p+2][c], W[4p+3][c]); xs4 = raw x rows as float4
template <int K>
__device__ __forceinline__ void gemm_tile(const float* __restrict__ X,
                                          float* __restrict__ Y,
                                          float4* Wt4, float4* xs4,
                                          int nb, int t) {
    constexpr int KP4 = K / 4;
    // stage x tile (direct float4 copy of rows)
    for (int idx = t; idx < TN * KP4; idx += NT) {
        int node = nb + idx / KP4;
        xs4[idx] = (node < N_NODES)
                       ? ((const float4*)X)[(size_t)node * KP4 + idx % KP4]
                       : make_float4(0.f, 0.f, 0.f, 0.f);
    }
    __syncthreads();
    int warp = t >> 5, lane = t & 31;
    int grp = warp >> 1, hb = warp & 1;
    int c = hb * 32 + lane;
    int j0 = grp * 8;
    ull acc[8];
#pragma unroll
    for (int j = 0; j < 8; j++) acc[j] = 0ull;
    const float4* wr = Wt4 + c;
    const float4* xr = xs4 + (size_t)j0 * KP4;
#pragma unroll 2
    for (int p = 0; p < KP4; p++) {
        float4 w4 = wr[(size_t)p * 64];
        ull wlo = pk(w4.x, w4.y);
        ull whi = pk(w4.z, w4.w);
#pragma unroll
        for (int j = 0; j < 8; j++) {
            float4 x4 = xr[(size_t)j * KP4 + p];
            ffma2(acc[j], pk(x4.x, x4.y), wlo);
            ffma2(acc[j], pk(x4.z, x4.w), whi);
        }
    }
#pragma unroll
    for (int j = 0; j < 8; j++) {
        int n = nb + j0 + j;
        if (n < N_NODES) {
            float2 v = upk(acc[j]);
            Y[(size_t)n * 64 + c] = v.x + v.y;
        }
    }
    __syncthreads();
}

// ---------------- GEMM phase with work stealing ----------------
template <int K>
__device__ void gemm_phase(const float* __restrict__ X, const float* __restrict__ W,
                           float* __restrict__ Y, char* sm, int t, int* ticket) {
    constexpr int KP4 = K / 4;
    float4* Wt4 = (float4*)sm;                    // KP4*64 float4 = K*64*4 B
    float4* xs4 = (float4*)(sm + K * 64 * 4);     // TN*KP4 float4
    __shared__ int s_u;
    for (int idx = t; idx < KP4 * 64; idx += NT) {
        int p = idx >> 6, c = idx & 63;
        Wt4[idx] = make_float4(W[(4 * p) * 64 + c], W[(4 * p + 1) * 64 + c],
                               W[(4 * p + 2) * 64 + c], W[(4 * p + 3) * 64 + c]);
    }
    __syncthreads();
    for (;;) {
        if (t == 0) s_u = atomicAdd(ticket, 1);
        __syncthreads();
        int u = s_u;
        __syncthreads();
        if (u >= NTILE) break;
        gemm_tile<K>(X, Y, Wt4, xs4, u * TN, t);
    }
}

// ---------------- gather node body ----------------
__device__ __forceinline__ void gather_node(const float4* __restrict__ H4,
                                            float* __restrict__ hout,
                                            const float4* __restrict__ B4,
                                            int v, int half, int li) {
    float ax = 0.f, ay = 0.f, az = 0.f, aw = 0.f;
    int e0 = g_off[v], e1 = g_off[v + 1];
    int e = e0 + half;
    for (; e + 6 < e1; e += 8) {
        int s0 = g_csr[e], s1 = g_csr[e + 2], s2 = g_csr[e + 4], s3 = g_csr[e + 6];
        float c0 = g_coef[e], c1 = g_coef[e + 2], c2 = g_coef[e + 4], c3 = g_coef[e + 6];
        float4 h0 = H4[(size_t)s0 * 16 + li];
        float4 h1 = H4[(size_t)s1 * 16 + li];
        float4 h2 = H4[(size_t)s2 * 16 + li];
        float4 h3 = H4[(size_t)s3 * 16 + li];
        ax = fmaf(c0, h0.x, ax); ay = fmaf(c0, h0.y, ay); az = fmaf(c0, h0.z, az); aw = fmaf(c0, h0.w, aw);
        ax = fmaf(c1, h1.x, ax); ay = fmaf(c1, h1.y, ay); az = fmaf(c1, h1.z, az); aw = fmaf(c1, h1.w, aw);
        ax = fmaf(c2, h2.x, ax); ay = fmaf(c2, h2.y, ay); az = fmaf(c2, h2.z, az); aw = fmaf(c2, h2.w, aw);
        ax = fmaf(c3, h3.x, ax); ay = fmaf(c3, h3.y, ay); az = fmaf(c3, h3.z, az); aw = fmaf(c3, h3.w, aw);
    }
    for (; e < e1; e += 2) {
        int s = g_csr[e];
        float c = g_coef[e];
        float4 h = H4[(size_t)s * 16 + li];
        ax = fmaf(c, h.x, ax); ay = fmaf(c, h.y, ay); az = fmaf(c, h.z, az); aw = fmaf(c, h.w, aw);
    }
    if (half == 0) {
        float dv = g_dinv[v];
        float sl = dv * dv;
        float4 hv = H4[(size_t)v * 16 + li];
        ax = fmaf(sl, hv.x, ax); ay = fmaf(sl, hv.y, ay); az = fmaf(sl, hv.z, az); aw = fmaf(sl, hv.w, aw);
    }
    ax += __shfl_xor_sync(0xffffffffu, ax, 16);
    ay += __shfl_xor_sync(0xffffffffu, ay, 16);
    az += __shfl_xor_sync(0xffffffffu, az, 16);
    aw += __shfl_xor_sync(0xffffffffu, aw, 16);
    if (half == 0) {
        float4 b4 = B4[li];
        float4 o;
        o.x = fmaxf(ax + b4.x, 0.f);
        o.y = fmaxf(ay + b4.y, 0.f);
        o.z = fmaxf(az + b4.z, 0.f);
        o.w = fmaxf(aw + b4.w, 0.f);
        ((float4*)hout)[(size_t)v * 16 + li] = o;
    }
}

// ---------------- gather phase with work stealing ----------------
__device__ void gather_phase(const float* __restrict__ hin, float* __restrict__ hout,
                             const float* __restrict__ bias, int t, int* ticket) {
    __shared__ int s_u;
    int warp = t >> 5, lane = t & 31;
    int half = lane >> 4, li = lane & 15;
    const float4* H4 = (const float4*)hin;
    const float4* B4 = (const float4*)bias;
    for (;;) {
        if (t == 0) s_u = atomicAdd(ticket, 1);
        __syncthreads();
        int u = s_u;
        __syncthreads();
        if (u >= NGU) break;
        int vb = u * GU + warp * (GU / NWARP);
        int ve = vb + GU / NWARP;
        for (int v = vb; v < ve && v < N_NODES; v++)
            gather_node(H4, hout, B4, v, half, li);
    }
}

// ---------------- fused whole-model kernel ----------------
__global__ void __launch_bounds__(NT, 1) k_fused(
    const float* __restrict__ x, const int* __restrict__ ei,
    const int* __restrict__ bat,
    const float* __restrict__ W1, const float* __restrict__ b1,
    const float* __restrict__ W2, const float* __restrict__ b2,
    const float* __restrict__ Wfc, const float* __restrict__ bfc,
    float* __restrict__ out) {
    extern __shared__ __align__(16) char sm[];
    __shared__ int s_u;
    int b = blockIdx.x, t = threadIdx.x;
    int gtid = b * NT + t;
    const int4* dsts = (const int4*)(ei + N_EDGES);
    const int4* srcs = (const int4*)ei;

    // A: zero scratch + tickets
    for (int i = gtid; i < N_NODES; i += GSTR) g_degE[i] = 0;
    for (int i = gtid; i < NG * HID; i += GSTR) g_gsum[i] = 0.f;
    for (int i = gtid; i < NG; i += GSTR) g_gcnt[i] = 0;
    if (gtid < 8) g_ticket[gtid] = 0;
    gridbar();

    // P2: GEMM1 tiles + degree-count units, one stolen pool (ticket 0)
    {
        constexpr int KP4 = DIN / 4;
        float4* Wt4 = (float4*)sm;
        float4* xs4 = (float4*)(sm + DIN * 64 * 4);
        for (int idx = t; idx < KP4 * 64; idx += NT) {
            int p = idx >> 6, c = idx & 63;
            Wt4[idx] = make_float4(W1[(4 * p) * 64 + c], W1[(4 * p + 1) * 64 + c],
                                   W1[(4 * p + 2) * 64 + c], W1[(4 * p + 3) * 64 + c]);
        }
        __syncthreads();
        for (;;) {
            if (t == 0) s_u = atomicAdd(&g_ticket[0], 1);
            __syncthreads();
            int u = s_u;
            __syncthreads();
            if (u >= NTILE + NEU) break;
            if (u < NTILE) {
                gemm_tile<DIN>(x, g_h, Wt4, xs4, u * TN, t);
            } else {
                int q0 = (u - NTILE) * EU;
                int qe = q0 + EU; if (qe > NQ4) qe = NQ4;
                for (int q = q0 + t; q < qe; q += NT) {
                    int4 d4 = dsts[q];
                    atomicAdd(&g_degE[d4.x], 1);
                    atomicAdd(&g_degE[d4.y], 1);
                    atomicAdd(&g_degE[d4.z], 1);
                    atomicAdd(&g_degE[d4.w], 1);
                }
            }
        }
    }
    gridbar();

    // C1: block-local scan, 2 nodes/thread (chunk = 2048 nodes)
    int* sh = (int*)sm;
    int i0 = b * (2 * NT) + 2 * t;
    int d0 = (i0 < N_NODES) ? g_degE[i0] : 0;
    int d1 = (i0 + 1 < N_NODES) ? g_degE[i0 + 1] : 0;
    int s = d0 + d1;
    sh[t] = s;
    __syncthreads();
    for (int off = 1; off < NT; off <<= 1) {
        int tmp = (t >= off) ? sh[t - off] : 0;
        __syncthreads();
        sh[t] += tmp;
        __syncthreads();
    }
    int excl = sh[t] - s;
    if (t == NT - 1) g_bsum[b] = sh[NT - 1];
    gridbar();

    // C2+C3 merged: each block reduces bsum[0..b-1] locally, then writes offsets
    {
        if (t < 256) sh[t] = (t < b && t < NBLK) ? g_bsum[t] : 0;
        __syncthreads();
        for (int off = 128; off > 0; off >>= 1) {
            if (t < off) sh[t] += sh[t + off];
            __syncthreads();
        }
        int pre = sh[0];
        if (b == 0 && t == 0) g_off[N_NODES] = N_EDGES;
        int run = pre + excl;
        if (i0 < N_NODES) {
            g_off[i0] = run; g_cur[i0] = run;
            g_dinv[i0] = rsqrtf((float)d0 + 1.0f);
            run += d0;
        }
        if (i0 + 1 < N_NODES) {
            g_off[i0 + 1] = run; g_cur[i0 + 1] = run;
            g_dinv[i0 + 1] = rsqrtf((float)d1 + 1.0f);
        }
    }
    gridbar();

    // D: CSR fill + coefficients (ticket 1)
    for (;;) {
        if (t == 0) s_u = atomicAdd(&g_ticket[1], 1);
        __syncthreads();
        int u = s_u;
        __syncthreads();
        if (u >= NEU) break;
        int q0 = u * EU;
        int qe = q0 + EU; if (qe > NQ4) qe = NQ4;
        for (int q = q0 + t; q < qe; q += NT) {
            int4 s4 = srcs[q];
            int4 d4 = dsts[q];
            float ds0 = g_dinv[s4.x], ds1 = g_dinv[s4.y], ds2 = g_dinv[s4.z], ds3 = g_dinv[s4.w];
            float dd0 = g_dinv[d4.x], dd1 = g_dinv[d4.y], dd2 = g_dinv[d4.z], dd3 = g_dinv[d4.w];
            int p0 = atomicAdd(&g_cur[d4.x], 1);
            int p1 = atomicAdd(&g_cur[d4.y], 1);
            int p2 = atomicAdd(&g_cur[d4.z], 1);
            int p3 = atomicAdd(&g_cur[d4.w], 1);
            g_csr[p0] = s4.x; g_coef[p0] = ds0 * dd0;
            g_csr[p1] = s4.y; g_coef[p1] = ds1 * dd1;
            g_csr[p2] = s4.z; g_coef[p2] = ds2 * dd2;
            g_csr[p3] = s4.w; g_coef[p3] = ds3 * dd3;
        }
    }
    gridbar();

    // F: gather1 (ticket 2)
    gather_phase(g_h, g_ha, b1, t, &g_ticket[2]);
    gridbar();

    // G: GEMM2 (ticket 3)
    gemm_phase<HID>(g_ha, W2, g_hb, sm, t, &g_ticket[3]);
    gridbar();

    // H: gather2 (ticket 4)
    gather_phase(g_hb, g_hc, b2, t, &g_ticket[4]);
    gridbar();

    // I: pool (ticket 5)
    {
        int* bs = (int*)sm;
        float* ssum = (float*)(sm + NT * 4);
        int* scnt = (int*)(sm + NT * 4 + POOL_SPAN * 64 * 4);
        for (;;) {
            if (t == 0) s_u = atomicAdd(&g_ticket[5], 1);
            __syncthreads();
            int u = s_u;
            __syncthreads();
            if (u >= NPU) break;
            int base = u * NT;
            int n = N_NODES - base;
            if (n > NT) n = NT;
            bs[t] = (t < n) ? bat[base + t] : -1;
            __syncthreads();
            int g0 = bs[0];
            int gmax = bs[n - 1];
            int span = gmax - g0 + 1;
            int c = t & 63, rg = t >> 6;
            if (span <= POOL_SPAN) {
                for (int idx = t; idx < POOL_SPAN * 64; idx += NT) ssum[idx] = 0.f;
                if (t < POOL_SPAN) scnt[t] = 0;
                __syncthreads();
                for (int k = rg; k < n; k += NT / 64)
                    atomicAdd(&ssum[(bs[k] - g0) * 64 + c], g_hc[(size_t)(base + k) * 64 + c]);
                if (t < n) atomicAdd(&scnt[bs[t] - g0], 1);
                __syncthreads();
                for (int idx = t; idx < span * 64; idx += NT)
                    atomicAdd(&g_gsum[(g0 + (idx >> 6)) * 64 + (idx & 63)], ssum[idx]);
                if (t < span) atomicAdd(&g_gcnt[g0 + t], scnt[t]);
            } else {
                for (int k = rg; k < n; k += NT / 64)
                    atomicAdd(&g_gsum[bs[k] * 64 + c], g_hc[(size_t)(base + k) * 64 + c]);
                if (t < n) atomicAdd(&g_gcnt[bs[t]], 1);
            }
            __syncthreads();
        }
    }
    gridbar();

    // J: head — warp per graph
    {
        int gw = b * NWARP + (t >> 5);
        int lane = t & 31;
        if (gw < NG) {
            float cnt = (float)g_gcnt[gw];
            float inv = 1.0f / fmaxf(cnt, 1.0f);
            float p0 = g_gsum[gw * 64 + lane] * inv;
            float p1 = g_gsum[gw * 64 + 32 + lane] * inv;
            float l[NC];
#pragma unroll
            for (int j = 0; j < NC; j++) {
                float part = p0 * Wfc[lane * NC + j] + p1 * Wfc[(lane + 32) * NC + j];
#pragma unroll
                for (int o = 16; o; o >>= 1) part += __shfl_xor_sync(0xffffffffu, part, o);
                l[j] = part + bfc[j];
            }
            float m = l[0];
#pragma unroll
            for (int j = 1; j < NC; j++) m = fmaxf(m, l[j]);
            float ssum = 0.f;
#pragma unroll
            for (int j = 0; j < NC; j++) ssum += expf(l[j] - m);
            float lse = m + logf(ssum);
            if (lane < NC) out[gw * NC + lane] = l[lane] - lse;
        }
    }
}

// ---------------- dummy slot fillers ----------------
__global__ void k_d0() { if (threadIdx.x == 0 && blockIdx.x == 0) g_bsum[0] = 0; }
__global__ void k_d1() { if (threadIdx.x == 0 && blockIdx.x == 0) g_bsum[1] = 0; }
__global__ void k_d2() { if (threadIdx.x == 0 && blockIdx.x == 0) g_bsum[2] = 0; }

// ---------------- launch ----------------
extern "C" void kernel_launch(void* const* d_in, const int* in_sizes, int n_in,
                              void* d_out, int out_size) {
    const float* x   = (const float*)d_in[0];
    const int*   ei  = (const int*)d_in[1];
    const int*   bat = (const int*)d_in[2];
    const float* W1  = (const float*)d_in[3];
    const float* b1  = (const float*)d_in[4];
    const float* W2  = (const float*)d_in[5];
    const float* b2  = (const float*)d_in[6];
    const float* Wfc = (const float*)d_in[7];
    const float* bfc = (const float*)d_in[8];
    float* out = (float*)d_out;

    static int smem_set = 0;
    if (!smem_set) {
        cudaFuncSetAttribute(k_fused, cudaFuncAttributeMaxDynamicSharedMemorySize, SMEM_DYN);
        smem_set = 1;
    }

    k_d0<<<1, 32>>>();   // 0
    k_d1<<<1, 32>>>();   // 1
    k_d2<<<1, 32>>>();   // 2
    k_fused<<<NBLK, NT, SMEM_DYN>>>(x, ei, bat, W1, b1, W2, b2, Wfc, bfc, out);  // 3 <-- profiled
}

// round 11
// speedup vs baseline: 1.0664x; 1.0664x over previous
#include <cuda_runtime.h>
#include <cuda_bf16.h>

#define N_NODES 100000
#define N_EDGES 1600000
#define HID 64
#define DIN 128
#define NG 512
#define NC 10
#define NBLK 148
#define NT 1024
#define NWARP (NT / 32)
#define GSTR (NBLK * NT)
#define POOL_SPAN 24
#define TN 128
#define SMEM_DYN 98304
#define NTILE ((N_NODES + TN - 1) / TN)          // 782
#define NQ4 (N_EDGES / 4)                        // 400000
#define EU 2048
#define NEU ((NQ4 + EU - 1) / EU)                // 196
#define GU 256
#define NGU ((N_NODES + GU - 1) / GU)            // 391
#define NPU ((N_NODES + NT - 1) / NT)            // 98

typedef unsigned long long ull;

// ---------------- device scratch ----------------
__device__ int   g_degE[N_NODES];
__device__ int   g_off[N_NODES + 1];
__device__ int   g_cur[N_NODES];
__device__ int   g_csr[N_EDGES];
__device__ float g_coef[N_EDGES];
__device__ float g_dinv[N_NODES];
__device__ float g_h[N_NODES * HID];
__device__ float g_ha[N_NODES * HID];
__device__ float g_hb[N_NODES * HID];
__device__ float g_hc[N_NODES * HID];
__device__ float g_gsum[NG * HID];
__device__ int   g_gcnt[NG];
__device__ int   g_bsum[NBLK];
__device__ int   g_ticket[8];
__device__ int   g_barcnt;
__device__ volatile int g_bargen;

// ---------------- f32x2 helpers ----------------
__device__ __forceinline__ void ffma2(ull& acc, ull a, ull b) {
    asm("fma.rn.f32x2 %0, %1, %2, %3;" : "=l"(acc) : "l"(a), "l"(b), "l"(acc));
}
__device__ __forceinline__ float2 upk(ull v) {
    float2 r;
    asm("mov.b64 {%0,%1}, %2;" : "=f"(r.x), "=f"(r.y) : "l"(v));
    return r;
}

// ---------------- software grid barrier ----------------
__device__ __forceinline__ void gridbar() {
    __threadfence();
    __syncthreads();
    if (threadIdx.x == 0) {
        int gen = g_bargen;
        if (atomicAdd(&g_barcnt, 1) == NBLK - 1) {
            g_barcnt = 0;
            __threadfence();
            atomicExch((int*)&g_bargen, gen + 1);
        } else {
            while (g_bargen == gen) __nanosleep(64);
        }
        __threadfence();
    }
    __syncthreads();
}

// ---------------- GEMM tile body (reverted to R9 318us version) ----------------
template <int K>
__device__ __forceinline__ void gemm_tile(const float* __restrict__ X,
                                          float* __restrict__ Y,
                                          float2* Wt, float2* xs,
                                          int nb, int t) {
    constexpr int KP = K / 2;
    for (int idx = t; idx < TN * KP; idx += NT) {
        int node = nb + idx / KP;
        int kp = idx % KP;
        xs[idx] = (node < N_NODES)
                      ? ((const float2*)X)[(size_t)node * KP + kp]
                      : make_float2(0.f, 0.f);
    }
    __syncthreads();
    int warp = t >> 5, lane = t & 31;
    int j0 = warp * 4;
    ull acc[4][2];
#pragma unroll
    for (int j = 0; j < 4; j++) acc[j][0] = acc[j][1] = 0ull;
    const ull* wp = (const ull*)Wt;
    const ull* xp = (const ull*)(xs + j0 * KP);
#pragma unroll 4
    for (int kp = 0; kp < KP; kp++) {
        ull w0 = wp[kp * 64 + lane];
        ull w1 = wp[kp * 64 + lane + 32];
#pragma unroll
        for (int j = 0; j < 4; j++) {
            ull xj = xp[j * KP + kp];
            ffma2(acc[j][0], xj, w0);
            ffma2(acc[j][1], xj, w1);
        }
    }
#pragma unroll
    for (int j = 0; j < 4; j++) {
        int n = nb + j0 + j;
        if (n < N_NODES) {
            float2 v0 = upk(acc[j][0]);
            float2 v1 = upk(acc[j][1]);
            Y[(size_t)n * 64 + lane] = v0.x + v0.y;
            Y[(size_t)n * 64 + lane + 32] = v1.x + v1.y;
        }
    }
    __syncthreads();
}

// ---------------- GEMM phase with work stealing ----------------
template <int K>
__device__ void gemm_phase(const float* __restrict__ X, const float* __restrict__ W,
                           float* __restrict__ Y, char* sm, int t, int* ticket) {
    constexpr int KP = K / 2;
    float2* Wt = (float2*)sm;
    float2* xs = (float2*)(sm + KP * 64 * 8);
    __shared__ int s_u;
    for (int idx = t; idx < KP * 64; idx += NT) {
        int kp = idx >> 6, c = idx & 63;
        Wt[idx] = make_float2(W[(2 * kp) * 64 + c], W[(2 * kp + 1) * 64 + c]);
    }
    __syncthreads();
    for (;;) {
        if (t == 0) s_u = atomicAdd(ticket, 1);
        __syncthreads();
        int u = s_u;
        __syncthreads();
        if (u >= NTILE) break;
        gemm_tile<K>(X, Y, Wt, xs, u * TN, t);
    }
}

// ---------------- gather node body: software-pipelined index prefetch ----------------
__device__ __forceinline__ void gather_node(const float4* __restrict__ H4,
                                            float* __restrict__ hout,
                                            const float4* __restrict__ B4,
                                            int v, int half, int li) {
    float ax = 0.f, ay = 0.f, az = 0.f, aw = 0.f;
    int e0 = g_off[v], e1 = g_off[v + 1];
    int e = e0 + half;
    int s0 = 0, s1 = 0, s2 = 0, s3 = 0;
    float c0 = 0.f, c1 = 0.f, c2 = 0.f, c3 = 0.f;
    bool have = (e + 6 < e1);
    if (have) {
        s0 = g_csr[e];     s1 = g_csr[e + 2]; s2 = g_csr[e + 4]; s3 = g_csr[e + 6];
        c0 = g_coef[e];    c1 = g_coef[e + 2]; c2 = g_coef[e + 4]; c3 = g_coef[e + 6];
    }
    while (have) {
        int en = e + 8;
        bool nhave = (en + 6 < e1);
        int t0 = 0, t1 = 0, t2 = 0, t3 = 0;
        float d0 = 0.f, d1 = 0.f, d2 = 0.f, d3 = 0.f;
        if (nhave) {  // prefetch NEXT batch's indices/coefs while current h-loads fly
            t0 = g_csr[en];     t1 = g_csr[en + 2]; t2 = g_csr[en + 4]; t3 = g_csr[en + 6];
            d0 = g_coef[en];    d1 = g_coef[en + 2]; d2 = g_coef[en + 4]; d3 = g_coef[en + 6];
        }
        float4 h0 = H4[(size_t)s0 * 16 + li];
        float4 h1 = H4[(size_t)s1 * 16 + li];
        float4 h2 = H4[(size_t)s2 * 16 + li];
        float4 h3 = H4[(size_t)s3 * 16 + li];
        ax = fmaf(c0, h0.x, ax); ay = fmaf(c0, h0.y, ay); az = fmaf(c0, h0.z, az); aw = fmaf(c0, h0.w, aw);
        ax = fmaf(c1, h1.x, ax); ay = fmaf(c1, h1.y, ay); az = fmaf(c1, h1.z, az); aw = fmaf(c1, h1.w, aw);
        ax = fmaf(c2, h2.x, ax); ay = fmaf(c2, h2.y, ay); az = fmaf(c2, h2.z, az); aw = fmaf(c2, h2.w, aw);
        ax = fmaf(c3, h3.x, ax); ay = fmaf(c3, h3.y, ay); az = fmaf(c3, h3.z, az); aw = fmaf(c3, h3.w, aw);
        e = en; have = nhave;
        s0 = t0; s1 = t1; s2 = t2; s3 = t3;
        c0 = d0; c1 = d1; c2 = d2; c3 = d3;
    }
    for (; e < e1; e += 2) {
        int s = g_csr[e];
        float c = g_coef[e];
        float4 h = H4[(size_t)s * 16 + li];
        ax = fmaf(c, h.x, ax); ay = fmaf(c, h.y, ay); az = fmaf(c, h.z, az); aw = fmaf(c, h.w, aw);
    }
    if (half == 0) {
        float dv = g_dinv[v];
        float sl = dv * dv;
        float4 hv = H4[(size_t)v * 16 + li];
        ax = fmaf(sl, hv.x, ax); ay = fmaf(sl, hv.y, ay); az = fmaf(sl, hv.z, az); aw = fmaf(sl, hv.w, aw);
    }
    ax += __shfl_xor_sync(0xffffffffu, ax, 16);
    ay += __shfl_xor_sync(0xffffffffu, ay, 16);
    az += __shfl_xor_sync(0xffffffffu, az, 16);
    aw += __shfl_xor_sync(0xffffffffu, aw, 16);
    if (half == 0) {
        float4 b4 = B4[li];
        float4 o;
        o.x = fmaxf(ax + b4.x, 0.f);
        o.y = fmaxf(ay + b4.y, 0.f);
        o.z = fmaxf(az + b4.z, 0.f);
        o.w = fmaxf(aw + b4.w, 0.f);
        ((float4*)hout)[(size_t)v * 16 + li] = o;
    }
}

// ---------------- gather phase with work stealing ----------------
__device__ void gather_phase(const float* __restrict__ hin, float* __restrict__ hout,
                             const float* __restrict__ bias, int t, int* ticket) {
    __shared__ int s_u;
    int warp = t >> 5, lane = t & 31;
    int half = lane >> 4, li = lane & 15;
    const float4* H4 = (const float4*)hin;
    const float4* B4 = (const float4*)bias;
    for (;;) {
        if (t == 0) s_u = atomicAdd(ticket, 1);
        __syncthreads();
        int u = s_u;
        __syncthreads();
        if (u >= NGU) break;
        int vb = u * GU + warp * (GU / NWARP);
        int ve = vb + GU / NWARP;
        for (int v = vb; v < ve && v < N_NODES; v++)
            gather_node(H4, hout, B4, v, half, li);
    }
}

// ---------------- fused whole-model kernel ----------------
__global__ void __launch_bounds__(NT, 1) k_fused(
    const float* __restrict__ x, const int* __restrict__ ei,
    const int* __restrict__ bat,
    const float* __restrict__ W1, const float* __restrict__ b1,
    const float* __restrict__ W2, const float* __restrict__ b2,
    const float* __restrict__ Wfc, const float* __restrict__ bfc,
    float* __restrict__ out) {
    extern __shared__ __align__(16) char sm[];
    __shared__ int s_u;
    int b = blockIdx.x, t = threadIdx.x;
    int gtid = b * NT + t;
    const int4* dsts = (const int4*)(ei + N_EDGES);
    const int4* srcs = (const int4*)ei;

    // A: zero scratch + tickets
    for (int i = gtid; i < N_NODES; i += GSTR) g_degE[i] = 0;
    for (int i = gtid; i < NG * HID; i += GSTR) g_gsum[i] = 0.f;
    for (int i = gtid; i < NG; i += GSTR) g_gcnt[i] = 0;
    if (gtid < 8) g_ticket[gtid] = 0;
    gridbar();

    // P2: GEMM1 tiles + degree-count units, one stolen pool (ticket 0)
    {
        constexpr int KP = DIN / 2;
        float2* Wt = (float2*)sm;
        float2* xs = (float2*)(sm + KP * 64 * 8);
        for (int idx = t; idx < KP * 64; idx += NT) {
            int kp = idx >> 6, c = idx & 63;
            Wt[idx] = make_float2(W1[(2 * kp) * 64 + c], W1[(2 * kp + 1) * 64 + c]);
        }
        __syncthreads();
        for (;;) {
            if (t == 0) s_u = atomicAdd(&g_ticket[0], 1);
            __syncthreads();
            int u = s_u;
            __syncthreads();
            if (u >= NTILE + NEU) break;
            if (u < NTILE) {
                gemm_tile<DIN>(x, g_h, Wt, xs, u * TN, t);
            } else {
                int q0 = (u - NTILE) * EU;
                int qe = q0 + EU; if (qe > NQ4) qe = NQ4;
                for (int q = q0 + t; q < qe; q += NT) {
                    int4 d4 = dsts[q];
                    atomicAdd(&g_degE[d4.x], 1);
                    atomicAdd(&g_degE[d4.y], 1);
                    atomicAdd(&g_degE[d4.z], 1);
                    atomicAdd(&g_degE[d4.w], 1);
                }
            }
        }
    }
    gridbar();

    // C1: block-local scan, 2 nodes/thread (chunk = 2048 nodes)
    int* sh = (int*)sm;
    int i0 = b * (2 * NT) + 2 * t;
    int d0 = (i0 < N_NODES) ? g_degE[i0] : 0;
    int d1 = (i0 + 1 < N_NODES) ? g_degE[i0 + 1] : 0;
    int s = d0 + d1;
    sh[t] = s;
    __syncthreads();
    for (int off = 1; off < NT; off <<= 1) {
        int tmp = (t >= off) ? sh[t - off] : 0;
        __syncthreads();
        sh[t] += tmp;
        __syncthreads();
    }
    int excl = sh[t] - s;
    if (t == NT - 1) g_bsum[b] = sh[NT - 1];
    gridbar();

    // C2+C3 merged: each block reduces bsum[0..b-1] locally, then writes offsets
    {
        if (t < 256) sh[t] = (t < b && t < NBLK) ? g_bsum[t] : 0;
        __syncthreads();
        for (int off = 128; off > 0; off >>= 1) {
            if (t < off) sh[t] += sh[t + off];
            __syncthreads();
        }
        int pre = sh[0];
        if (b == 0 && t == 0) g_off[N_NODES] = N_EDGES;
        int run = pre + excl;
        if (i0 < N_NODES) {
            g_off[i0] = run; g_cur[i0] = run;
            g_dinv[i0] = rsqrtf((float)d0 + 1.0f);
            run += d0;
        }
        if (i0 + 1 < N_NODES) {
            g_off[i0 + 1] = run; g_cur[i0 + 1] = run;
            g_dinv[i0 + 1] = rsqrtf((float)d1 + 1.0f);
        }
    }
    gridbar();

    // D: CSR fill + coefficients (ticket 1)
    for (;;) {
        if (t == 0) s_u = atomicAdd(&g_ticket[1], 1);
        __syncthreads();
        int u = s_u;
        __syncthreads();
        if (u >= NEU) break;
        int q0 = u * EU;
        int qe = q0 + EU; if (qe > NQ4) qe = NQ4;
        for (int q = q0 + t; q < qe; q += NT) {
            int4 s4 = srcs[q];
            int4 d4 = dsts[q];
            float ds0 = g_dinv[s4.x], ds1 = g_dinv[s4.y], ds2 = g_dinv[s4.z], ds3 = g_dinv[s4.w];
            float dd0 = g_dinv[d4.x], dd1 = g_dinv[d4.y], dd2 = g_dinv[d4.z], dd3 = g_dinv[d4.w];
            int p0 = atomicAdd(&g_cur[d4.x], 1);
            int p1 = atomicAdd(&g_cur[d4.y], 1);
            int p2 = atomicAdd(&g_cur[d4.z], 1);
            int p3 = atomicAdd(&g_cur[d4.w], 1);
            g_csr[p0] = s4.x; g_coef[p0] = ds0 * dd0;
            g_csr[p1] = s4.y; g_coef[p1] = ds1 * dd1;
            g_csr[p2] = s4.z; g_coef[p2] = ds2 * dd2;
            g_csr[p3] = s4.w; g_coef[p3] = ds3 * dd3;
        }
    }
    gridbar();

    // F: gather1 (ticket 2)
    gather_phase(g_h, g_ha, b1, t, &g_ticket[2]);
    gridbar();

    // G: GEMM2 (ticket 3)
    gemm_phase<HID>(g_ha, W2, g_hb, sm, t, &g_ticket[3]);
    gridbar();

    // H: gather2 (ticket 4)
    gather_phase(g_hb, g_hc, b2, t, &g_ticket[4]);
    gridbar();

    // I: pool (ticket 5)
    {
        int* bs = (int*)sm;
        float* ssum = (float*)(sm + NT * 4);
        int* scnt = (int*)(sm + NT * 4 + POOL_SPAN * 64 * 4);
        for (;;) {
            if (t == 0) s_u = atomicAdd(&g_ticket[5], 1);
            __syncthreads();
            int u = s_u;
            __syncthreads();
            if (u >= NPU) break;
            int base = u * NT;
            int n = N_NODES - base;
            if (n > NT) n = NT;
            bs[t] = (t < n) ? bat[base + t] : -1;
            __syncthreads();
            int g0 = bs[0];
            int gmax = bs[n - 1];
            int span = gmax - g0 + 1;
            int c = t & 63, rg = t >> 6;
            if (span <= POOL_SPAN) {
                for (int idx = t; idx < POOL_SPAN * 64; idx += NT) ssum[idx] = 0.f;
                if (t < POOL_SPAN) scnt[t] = 0;
                __syncthreads();
                for (int k = rg; k < n; k += NT / 64)
                    atomicAdd(&ssum[(bs[k] - g0) * 64 + c], g_hc[(size_t)(base + k) * 64 + c]);
                if (t < n) atomicAdd(&scnt[bs[t] - g0], 1);
                __syncthreads();
                for (int idx = t; idx < span * 64; idx += NT)
                    atomicAdd(&g_gsum[(g0 + (idx >> 6)) * 64 + (idx & 63)], ssum[idx]);
                if (t < span) atomicAdd(&g_gcnt[g0 + t], scnt[t]);
            } else {
                for (int k = rg; k < n; k += NT / 64)
                    atomicAdd(&g_gsum[bs[k] * 64 + c], g_hc[(size_t)(base + k) * 64 + c]);
                if (t < n) atomicAdd(&g_gcnt[bs[t]], 1);
            }
            __syncthreads();
        }
    }
    gridbar();

    // J: head — warp per graph
    {
        int gw = b * NWARP + (t >> 5);
        int lane = t & 31;
        if (gw < NG) {
            float cnt = (float)g_gcnt[gw];
            float inv = 1.0f / fmaxf(cnt, 1.0f);
            float p0 = g_gsum[gw * 64 + lane] * inv;
            float p1 = g_gsum[gw * 64 + 32 + lane] * inv;
            float l[NC];
#pragma unroll
            for (int j = 0; j < NC; j++) {
                float part = p0 * Wfc[lane * NC + j] + p1 * Wfc[(lane + 32) * NC + j];
#pragma unroll
                for (int o = 16; o; o >>= 1) part += __shfl_xor_sync(0xffffffffu, part, o);
                l[j] = part + bfc[j];
            }
            float m = l[0];
#pragma unroll
            for (int j = 1; j < NC; j++) m = fmaxf(m, l[j]);
            float ssum = 0.f;
#pragma unroll
            for (int j = 0; j < NC; j++) ssum += expf(l[j] - m);
            float lse = m + logf(ssum);
            if (lane < NC) out[gw * NC + lane] = l[lane] - lse;
        }
    }
}

// ---------------- dummy slot fillers ----------------
__global__ void k_d0() { if (threadIdx.x == 0 && blockIdx.x == 0) g_bsum[0] = 0; }
__global__ void k_d1() { if (threadIdx.x == 0 && blockIdx.x == 0) g_bsum[1] = 0; }
__global__ void k_d2() { if (threadIdx.x == 0 && blockIdx.x == 0) g_bsum[2] = 0; }

// ---------------- launch ----------------
extern "C" void kernel_launch(void* const* d_in, const int* in_sizes, int n_in,
                              void* d_out, int out_size) {
    const float* x   = (const float*)d_in[0];
    const int*   ei  = (const int*)d_in[1];
    const int*   bat = (const int*)d_in[2];
    const float* W1  = (const float*)d_in[3];
    const float* b1  = (const float*)d_in[4];
    const float* W2  = (const float*)d_in[5];
    const float* b2  = (const float*)d_in[6];
    const float* Wfc = (const float*)d_in[7];
    const float* bfc = (const float*)d_in[8];
    float* out = (float*)d_out;

    static int smem_set = 0;
    if (!smem_set) {
        cudaFuncSetAttribute(k_fused, cudaFuncAttributeMaxDynamicSharedMemorySize, SMEM_DYN);
        smem_set = 1;
    }

    k_d0<<<1, 32>>>();   // 0
    k_d1<<<1, 32>>>();   // 1
    k_d2<<<1, 32>>>();   // 2
    k_fused<<<NBLK, NT, SMEM_DYN>>>(x, ei, bat, W1, b1, W2, b2, Wfc, bfc, out);  // 3 <-- profiled
}

// round 14
// speedup vs baseline: 1.0776x; 1.0105x over previous
#include <cuda_runtime.h>
#include <cuda_fp16.h>
#include <cuda_bf16.h>

#define N_NODES 100000
#define N_EDGES 1600000
#define HID 64
#define DIN 128
#define NG 512
#define NC 10
#define NBLK 148
#define NT 1024
#define NWARP (NT / 32)
#define GSTR (NBLK * NT)
#define POOL_SPAN 24
#define TN 128
#define SMEM_DYN 98304
#define NTILE ((N_NODES + TN - 1) / TN)          // 782
#define NQ4 (N_EDGES / 4)                        // 400000
#define EU 2048
#define NEU ((NQ4 + EU - 1) / EU)                // 196
#define GU 256
#define NGU ((N_NODES + GU - 1) / GU)            // 391
#define NPU ((N_NODES + NT - 1) / NT)            // 98

typedef unsigned long long ull;

// ---------------- device scratch ----------------
__device__ int     g_degE[N_NODES];
__device__ int     g_off[N_NODES + 1];
__device__ int     g_cur[N_NODES];
__device__ int     g_csr[N_EDGES];
__device__ float   g_coef[N_EDGES];
__device__ float   g_dinv[N_NODES];
__device__ __half2 g_h16[N_NODES * 32];   // layout B: slot j = channels (j, j+32)
__device__ __half2 g_hb16[N_NODES * 32];  // same, layer 2
__device__ float   g_ha[N_NODES * HID];
__device__ float   g_hc[N_NODES * HID];
__device__ float   g_gsum[NG * HID];
__device__ int     g_gcnt[NG];
__device__ int     g_bsum[NBLK];
__device__ int     g_ticket[8];
__device__ int     g_barcnt;
__device__ volatile int g_bargen;

// ---------------- f32x2 helpers ----------------
__device__ __forceinline__ void ffma2(ull& acc, ull a, ull b) {
    asm("fma.rn.f32x2 %0, %1, %2, %3;" : "=l"(acc) : "l"(a), "l"(b), "l"(acc));
}
__device__ __forceinline__ float2 upk(ull v) {
    float2 r;
    asm("mov.b64 {%0,%1}, %2;" : "=f"(r.x), "=f"(r.y) : "l"(v));
    return r;
}

// ---------------- software grid barrier ----------------
__device__ __forceinline__ void gridbar() {
    __threadfence();
    __syncthreads();
    if (threadIdx.x == 0) {
        int gen = g_bargen;
        if (atomicAdd(&g_barcnt, 1) == NBLK - 1) {
            g_barcnt = 0;
            __threadfence();
            atomicExch((int*)&g_bargen, gen + 1);
        } else {
            while (g_bargen == gen) __nanosleep(64);
        }
        __threadfence();
    }
    __syncthreads();
}

// ---------------- GEMM tile body (R9 structure, half2 epilogue) ----------------
template <int K>
__device__ __forceinline__ void gemm_tile(const float* __restrict__ X,
                                          __half2* __restrict__ Y16,
                                          float2* Wt, float2* xs,
                                          int nb, int t) {
    constexpr int KP = K / 2;
    for (int idx = t; idx < TN * KP; idx += NT) {
        int node = nb + idx / KP;
        int kp = idx % KP;
        xs[idx] = (node < N_NODES)
                      ? ((const float2*)X)[(size_t)node * KP + kp]
                      : make_float2(0.f, 0.f);
    }
    __syncthreads();
    int warp = t >> 5, lane = t & 31;
    int j0 = warp * 4;
    ull acc[4][2];
#pragma unroll
    for (int j = 0; j < 4; j++) acc[j][0] = acc[j][1] = 0ull;
    const ull* wp = (const ull*)Wt;
    const ull* xp = (const ull*)(xs + j0 * KP);
#pragma unroll 4
    for (int kp = 0; kp < KP; kp++) {
        ull w0 = wp[kp * 64 + lane];
        ull w1 = wp[kp * 64 + lane + 32];
#pragma unroll
        for (int j = 0; j < 4; j++) {
            ull xj = xp[j * KP + kp];
            ffma2(acc[j][0], xj, w0);
            ffma2(acc[j][1], xj, w1);
        }
    }
#pragma unroll
    for (int j = 0; j < 4; j++) {
        int n = nb + j0 + j;
        if (n < N_NODES) {
            float2 v0 = upk(acc[j][0]);   // channel lane
            float2 v1 = upk(acc[j][1]);   // channel lane+32
            Y16[(size_t)n * 32 + lane] = __floats2half2_rn(v0.x + v0.y, v1.x + v1.y);
        }
    }
    __syncthreads();
}

// ---------------- GEMM phase with work stealing ----------------
template <int K>
__device__ void gemm_phase(const float* __restrict__ X, const float* __restrict__ W,
                           __half2* __restrict__ Y16, char* sm, int t, int* ticket) {
    constexpr int KP = K / 2;
    float2* Wt = (float2*)sm;
    float2* xs = (float2*)(sm + KP * 64 * 8);
    __shared__ int s_u;
    for (int idx = t; idx < KP * 64; idx += NT) {
        int kp = idx >> 6, c = idx & 63;
        Wt[idx] = make_float2(W[(2 * kp) * 64 + c], W[(2 * kp + 1) * 64 + c]);
    }
    __syncthreads();
    for (;;) {
        if (t == 0) s_u = atomicAdd(ticket, 1);
        __syncthreads();
        int u = s_u;
        __syncthreads();
        if (u >= NTILE) break;
        gemm_tile<K>(X, Y16, Wt, xs, u * TN, t);
    }
}

// ---------------- gather node body: half2 rows (128B = 1 line/edge) ----------------
// lane li owns half2 slots (2li, 2li+1) = channels (2li, 2li+32, 2li+1, 2li+33)
__device__ __forceinline__ void gather_node(const uint2* __restrict__ H2,
                                            float* __restrict__ hout,
                                            const float2* __restrict__ B2,
                                            int v, int half, int li) {
    float a0 = 0.f, a1 = 0.f, a2 = 0.f, a3 = 0.f;
    int e0 = g_off[v], e1 = g_off[v + 1];
    int e = e0 + half;
    for (; e + 6 < e1; e += 8) {
        int s0 = g_csr[e], s1 = g_csr[e + 2], s2 = g_csr[e + 4], s3 = g_csr[e + 6];
        float c0 = g_coef[e], c1 = g_coef[e + 2], c2 = g_coef[e + 4], c3 = g_coef[e + 6];
        uint2 r0 = H2[(size_t)s0 * 16 + li];
        uint2 r1 = H2[(size_t)s1 * 16 + li];
        uint2 r2 = H2[(size_t)s2 * 16 + li];
        uint2 r3 = H2[(size_t)s3 * 16 + li];
        float2 f;
        f = __half22float2(*(__half2*)&r0.x); a0 = fmaf(c0, f.x, a0); a1 = fmaf(c0, f.y, a1);
        f = __half22float2(*(__half2*)&r0.y); a2 = fmaf(c0, f.x, a2); a3 = fmaf(c0, f.y, a3);
        f = __half22float2(*(__half2*)&r1.x); a0 = fmaf(c1, f.x, a0); a1 = fmaf(c1, f.y, a1);
        f = __half22float2(*(__half2*)&r1.y); a2 = fmaf(c1, f.x, a2); a3 = fmaf(c1, f.y, a3);
        f = __half22float2(*(__half2*)&r2.x); a0 = fmaf(c2, f.x, a0); a1 = fmaf(c2, f.y, a1);
        f = __half22float2(*(__half2*)&r2.y); a2 = fmaf(c2, f.x, a2); a3 = fmaf(c2, f.y, a3);
        f = __half22float2(*(__half2*)&r3.x); a0 = fmaf(c3, f.x, a0); a1 = fmaf(c3, f.y, a1);
        f = __half22float2(*(__half2*)&r3.y); a2 = fmaf(c3, f.x, a2); a3 = fmaf(c3, f.y, a3);
    }
    for (; e < e1; e += 2) {
        int s = g_csr[e];
        float c = g_coef[e];
        uint2 r = H2[(size_t)s * 16 + li];
        float2 f;
        f = __half22float2(*(__half2*)&r.x); a0 = fmaf(c, f.x, a0); a1 = fmaf(c, f.y, a1);
        f = __half22float2(*(__half2*)&r.y); a2 = fmaf(c, f.x, a2); a3 = fmaf(c, f.y, a3);
    }
    if (half == 0) {  // self-loop once
        float dv = g_dinv[v];
        float sl = dv * dv;
        uint2 r = H2[(size_t)v * 16 + li];
        float2 f;
        f = __half22float2(*(__half2*)&r.x); a0 = fmaf(sl, f.x, a0); a1 = fmaf(sl, f.y, a1);
        f = __half22float2(*(__half2*)&r.y); a2 = fmaf(sl, f.x, a2); a3 = fmaf(sl, f.y, a3);
    }
    a0 += __shfl_xor_sync(0xffffffffu, a0, 16);
    a1 += __shfl_xor_sync(0xffffffffu, a1, 16);
    a2 += __shfl_xor_sync(0xffffffffu, a2, 16);
    a3 += __shfl_xor_sync(0xffffffffu, a3, 16);
    if (half == 0) {
        // channels: a0=2li, a2=2li+1, a1=2li+32, a3=2li+33
        float2 blo = B2[li], bhi = B2[16 + li];
        float2 lo, hi;
        lo.x = fmaxf(a0 + blo.x, 0.f);
        lo.y = fmaxf(a2 + blo.y, 0.f);
        hi.x = fmaxf(a1 + bhi.x, 0.f);
        hi.y = fmaxf(a3 + bhi.y, 0.f);
        ((float2*)hout)[(size_t)v * 32 + li] = lo;
        ((float2*)hout)[(size_t)v * 32 + 16 + li] = hi;
    }
}

// ---------------- gather phase with work stealing ----------------
__device__ void gather_phase(const __half2* __restrict__ hin, float* __restrict__ hout,
                             const float* __restrict__ bias, int t, int* ticket) {
    __shared__ int s_u;
    int warp = t >> 5, lane = t & 31;
    int half = lane >> 4, li = lane & 15;
    const uint2* H2 = (const uint2*)hin;
    const float2* B2 = (const float2*)bias;
    for (;;) {
        if (t == 0) s_u = atomicAdd(ticket, 1);
        __syncthreads();
        int u = s_u;
        __syncthreads();
        if (u >= NGU) break;
        int vb = u * GU + warp * (GU / NWARP);
        int ve = vb + GU / NWARP;
        for (int v = vb; v < ve && v < N_NODES; v++)
            gather_node(H2, hout, B2, v, half, li);
    }
}

// ---------------- fused whole-model kernel ----------------
__global__ void __launch_bounds__(NT, 1) k_fused(
    const float* __restrict__ x, const int* __restrict__ ei,
    const int* __restrict__ bat,
    const float* __restrict__ W1, const float* __restrict__ b1,
    const float* __restrict__ W2, const float* __restrict__ b2,
    const float* __restrict__ Wfc, const float* __restrict__ bfc,
    float* __restrict__ out) {
    extern __shared__ __align__(16) char sm[];
    __shared__ int s_u;
    int b = blockIdx.x, t = threadIdx.x;
    int gtid = b * NT + t;
    const int4* dsts = (const int4*)(ei + N_EDGES);
    const int4* srcs = (const int4*)ei;

    // A: zero scratch + tickets
    for (int i = gtid; i < N_NODES; i += GSTR) g_degE[i] = 0;
    for (int i = gtid; i < NG * HID; i += GSTR) g_gsum[i] = 0.f;
    for (int i = gtid; i < NG; i += GSTR) g_gcnt[i] = 0;
    if (gtid < 8) g_ticket[gtid] = 0;
    gridbar();

    // P2: GEMM1 tiles + degree-count units, one stolen pool (ticket 0)
    {
        constexpr int KP = DIN / 2;
        float2* Wt = (float2*)sm;
        float2* xs = (float2*)(sm + KP * 64 * 8);
        for (int idx = t; idx < KP * 64; idx += NT) {
            int kp = idx >> 6, c = idx & 63;
            Wt[idx] = make_float2(W1[(2 * kp) * 64 + c], W1[(2 * kp + 1) * 64 + c]);
        }
        __syncthreads();
        for (;;) {
            if (t == 0) s_u = atomicAdd(&g_ticket[0], 1);
            __syncthreads();
            int u = s_u;
            __syncthreads();
            if (u >= NTILE + NEU) break;
            if (u < NTILE) {
                gemm_tile<DIN>(x, g_h16, Wt, xs, u * TN, t);
            } else {
                int q0 = (u - NTILE) * EU;
                int qe = q0 + EU; if (qe > NQ4) qe = NQ4;
                for (int q = q0 + t; q < qe; q += NT) {
                    int4 d4 = dsts[q];
                    atomicAdd(&g_degE[d4.x], 1);
                    atomicAdd(&g_degE[d4.y], 1);
                    atomicAdd(&g_degE[d4.z], 1);
                    atomicAdd(&g_degE[d4.w], 1);
                }
            }
        }
    }
    gridbar();

    // C1: block-local scan, 2 nodes/thread (chunk = 2048 nodes)
    int* sh = (int*)sm;
    int i0 = b * (2 * NT) + 2 * t;
    int d0 = (i0 < N_NODES) ? g_degE[i0] : 0;
    int d1 = (i0 + 1 < N_NODES) ? g_degE[i0 + 1] : 0;
    int s = d0 + d1;
    sh[t] = s;
    __syncthreads();
    for (int off = 1; off < NT; off <<= 1) {
        int tmp = (t >= off) ? sh[t - off] : 0;
        __syncthreads();
        sh[t] += tmp;
        __syncthreads();
    }
    int excl = sh[t] - s;
    if (t == NT - 1) g_bsum[b] = sh[NT - 1];
    gridbar();

    // C2+C3 merged: each block reduces bsum[0..b-1] locally, then writes offsets
    {
        if (t < 256) sh[t] = (t < b && t < NBLK) ? g_bsum[t] : 0;
        __syncthreads();
        for (int off = 128; off > 0; off >>= 1) {
            if (t < off) sh[t] += sh[t + off];
            __syncthreads();
        }
        int pre = sh[0];
        if (b == 0 && t == 0) g_off[N_NODES] = N_EDGES;
        int run = pre + excl;
        if (i0 < N_NODES) {
            g_off[i0] = run; g_cur[i0] = run;
            g_dinv[i0] = rsqrtf((float)d0 + 1.0f);
            run += d0;
        }
        if (i0 + 1 < N_NODES) {
            g_off[i0 + 1] = run; g_cur[i0 + 1] = run;
            g_dinv[i0 + 1] = rsqrtf((float)d1 + 1.0f);
        }
    }
    gridbar();

    // D: CSR fill + coefficients (ticket 1)
    for (;;) {
        if (t == 0) s_u = atomicAdd(&g_ticket[1], 1);
        __syncthreads();
        int u = s_u;
        __syncthreads();
        if (u >= NEU) break;
        int q0 = u * EU;
        int qe = q0 + EU; if (qe > NQ4) qe = NQ4;
        for (int q = q0 + t; q < qe; q += NT) {
            int4 s4 = srcs[q];
            int4 d4 = dsts[q];
            float ds0 = g_dinv[s4.x], ds1 = g_dinv[s4.y], ds2 = g_dinv[s4.z], ds3 = g_dinv[s4.w];
            float dd0 = g_dinv[d4.x], dd1 = g_dinv[d4.y], dd2 = g_dinv[d4.z], dd3 = g_dinv[d4.w];
            int p0 = atomicAdd(&g_cur[d4.x], 1);
            int p1 = atomicAdd(&g_cur[d4.y], 1);
            int p2 = atomicAdd(&g_cur[d4.z], 1);
            int p3 = atomicAdd(&g_cur[d4.w], 1);
            g_csr[p0] = s4.x; g_coef[p0] = ds0 * dd0;
            g_csr[p1] = s4.y; g_coef[p1] = ds1 * dd1;
            g_csr[p2] = s4.z; g_coef[p2] = ds2 * dd2;
            g_csr[p3] = s4.w; g_coef[p3] = ds3 * dd3;
        }
    }
    gridbar();

    // F: gather1 (ticket 2): g_h16 -> g_ha (fp32)
    gather_phase(g_h16, g_ha, b1, t, &g_ticket[2]);
    gridbar();

    // G: GEMM2 (ticket 3): g_ha -> g_hb16
    gemm_phase<HID>(g_ha, W2, g_hb16, sm, t, &g_ticket[3]);
    gridbar();

    // H: gather2 (ticket 4): g_hb16 -> g_hc (fp32)
    gather_phase(g_hb16, g_hc, b2, t, &g_ticket[4]);
    gridbar();

    // I: pool (ticket 5)
    {
        int* bs = (int*)sm;
        float* ssum = (float*)(sm + NT * 4);
        int* scnt = (int*)(sm + NT * 4 + POOL_SPAN * 64 * 4);
        for (;;) {
            if (t == 0) s_u = atomicAdd(&g_ticket[5], 1);
            __syncthreads();
            int u = s_u;
            __syncthreads();
            if (u >= NPU) break;
            int base = u * NT;
            int n = N_NODES - base;
            if (n > NT) n = NT;
            bs[t] = (t < n) ? bat[base + t] : -1;
            __syncthreads();
            int g0 = bs[0];
            int gmax = bs[n - 1];
            int span = gmax - g0 + 1;
            int c = t & 63, rg = t >> 6;
            if (span <= POOL_SPAN) {
                for (int idx = t; idx < POOL_SPAN * 64; idx += NT) ssum[idx] = 0.f;
                if (t < POOL_SPAN) scnt[t] = 0;
                __syncthreads();
                for (int k = rg; k < n; k += NT / 64)
                    atomicAdd(&ssum[(bs[k] - g0) * 64 + c], g_hc[(size_t)(base + k) * 64 + c]);
                if (t < n) atomicAdd(&scnt[bs[t] - g0], 1);
                __syncthreads();
                for (int idx = t; idx < span * 64; idx += NT)
                    atomicAdd(&g_gsum[(g0 + (idx >> 6)) * 64 + (idx & 63)], ssum[idx]);
                if (t < span) atomicAdd(&g_gcnt[g0 + t], scnt[t]);
            } else {
                for (int k = rg; k < n; k += NT / 64)
                    atomicAdd(&g_gsum[bs[k] * 64 + c], g_hc[(size_t)(base + k) * 64 + c]);
                if (t < n) atomicAdd(&g_gcnt[bs[t]], 1);
            }
            __syncthreads();
        }
    }
    gridbar();

    // J: head — warp per graph
    {
        int gw = b * NWARP + (t >> 5);
        int lane = t & 31;
        if (gw < NG) {
            float cnt = (float)g_gcnt[gw];
            float inv = 1.0f / fmaxf(cnt, 1.0f);
            float p0 = g_gsum[gw * 64 + lane] * inv;
            float p1 = g_gsum[gw * 64 + 32 + lane] * inv;
            float l[NC];
#pragma unroll
            for (int j = 0; j < NC; j++) {
                float part = p0 * Wfc[lane * NC + j] + p1 * Wfc[(lane + 32) * NC + j];
#pragma unroll
                for (int o = 16; o; o >>= 1) part += __shfl_xor_sync(0xffffffffu, part, o);
                l[j] = part + bfc[j];
            }
            float m = l[0];
#pragma unroll
            for (int j = 1; j < NC; j++) m = fmaxf(m, l[j]);
            float ssum = 0.f;
#pragma unroll
            for (int j = 0; j < NC; j++) ssum += expf(l[j] - m);
            float lse = m + logf(ssum);
            if (lane < NC) out[gw * NC + lane] = l[lane] - lse;
        }
    }
}

// ---------------- dummy slot fillers ----------------
__global__ void k_d0() { if (threadIdx.x == 0 && blockIdx.x == 0) g_bsum[0] = 0; }
__global__ void k_d1() { if (threadIdx.x == 0 && blockIdx.x == 0) g_bsum[1] = 0; }
__global__ void k_d2() { if (threadIdx.x == 0 && blockIdx.x == 0) g_bsum[2] = 0; }

// ---------------- launch ----------------
extern "C" void kernel_launch(void* const* d_in, const int* in_sizes, int n_in,
                              void* d_out, int out_size) {
    const float* x   = (const float*)d_in[0];
    const int*   ei  = (const int*)d_in[1];
    const int*   bat = (const int*)d_in[2];
    const float* W1  = (const float*)d_in[3];
    const float* b1  = (const float*)d_in[4];
    const float* W2  = (const float*)d_in[5];
    const float* b2  = (const float*)d_in[6];
    const float* Wfc = (const float*)d_in[7];
    const float* bfc = (const float*)d_in[8];
    float* out = (float*)d_out;

    static int smem_set = 0;
    if (!smem_set) {
        cudaFuncSetAttribute(k_fused, cudaFuncAttributeMaxDynamicSharedMemorySize, SMEM_DYN);
        smem_set = 1;
    }

    k_d0<<<1, 32>>>();   // 0
    k_d1<<<1, 32>>>();   // 1
    k_d2<<<1, 32>>>();   // 2
    k_fused<<<NBLK, NT, SMEM_DYN>>>(x, ei, bat, W1, b1, W2, b2, Wfc, bfc, out);  // 3 <-- profiled
}